// round 1
// baseline (speedup 1.0000x reference)
#include <cuda_runtime.h>
#include <cstdint>

#define NT   8192
#define DIMD 2048
#define HID  1408
#define NE   8
#define CAP  (NT/NE)   // 1024

#define BM 128
#define BN 64
#define BK 32
#define THREADS 256

// fp32 scratch for the intermediate h = silu(x@w1^T) * (x@w3^T), indexed by
// expert slot (e*CAP + i) so pass2 doesn't need the (clamped) token offsets.
__device__ float g_h[(size_t)NT * HID];

// round-to-nearest fp32 -> tf32 (keeps bit pattern in a 32-bit reg)
__device__ __forceinline__ uint32_t f2tf(float f) {
    uint32_t u;
    asm("cvt.rna.tf32.f32 %0, %1;" : "=r"(u) : "f"(f));
    return u;
}

// Swizzled smem layout for a [rows][BK=32] fp32 tile:
//   word index = r*32 + ((c>>2) ^ (r&7))*4 + (c&3)
// -> conflict-free 16B STS and conflict-free scalar fragment LDS.
__device__ __forceinline__ int sidx(int r, int c) {
    return r * BK + ((((c >> 2) ^ (r & 7))) << 2) + (c & 3);
}
__device__ __forceinline__ int schunk(int r, int k4) {
    return r * BK + ((k4 ^ (r & 7)) << 2);
}

__device__ __forceinline__ void mma8(float* d, const uint32_t* a, const uint32_t* b) {
    asm volatile(
        "mma.sync.aligned.m16n8k8.row.col.f32.tf32.tf32.f32 "
        "{%0,%1,%2,%3}, {%4,%5,%6,%7}, {%8,%9}, {%0,%1,%2,%3};"
        : "+f"(d[0]), "+f"(d[1]), "+f"(d[2]), "+f"(d[3])
        : "r"(a[0]), "r"(a[1]), "r"(a[2]), "r"(a[3]), "r"(b[0]), "r"(b[1]));
}

// ---------------------------------------------------------------------------
// Pass 1: per-expert fused gate-up. h = silu(x@w1e^T) * (x@w3e^T)
// grid: (HID/BN=22, CAP/BM=8, NE=8), block 256, dyn smem 64KB
// ---------------------------------------------------------------------------
__global__ void __launch_bounds__(THREADS, 1) moe_up(
    const float* __restrict__ x, const int* __restrict__ cnts,
    const float* __restrict__ w1, const float* __restrict__ w3)
{
    extern __shared__ uint32_t sm[];
    uint32_t* sx = sm;           // 2 * 4096 words (x tile, 128x32)
    uint32_t* s1 = sm + 8192;    // 2 * 2048 words (w1 tile, 64x32)
    uint32_t* s3 = sm + 12288;   // 2 * 2048 words (w3 tile, 64x32)

    const int e  = blockIdx.z;
    const int n0 = blockIdx.x * BN;
    const int m0 = blockIdx.y * BM;

    int start = 0;
#pragma unroll
    for (int j = 0; j < NE; j++) { int c = cnts[j]; if (j < e) start += c; }
    const int start_cl = min(start, NT - CAP);   // dynamic_slice clamping

    const float* xg  = x  + (size_t)(start_cl + m0) * DIMD;
    const float* w1g = w1 + (size_t)e * HID * DIMD + (size_t)n0 * DIMD;
    const float* w3g = w3 + (size_t)e * HID * DIMD + (size_t)n0 * DIMD;

    const int tid  = threadIdx.x;
    const int warp = tid >> 5, lane = tid & 31;
    const int wm = warp >> 1, wn = warp & 1;          // 4 m-warps x 2 n-warps
    const int g = lane >> 2, tg = lane & 3;

    float acc1[2][4][4], acc3[2][4][4];
#pragma unroll
    for (int i = 0; i < 2; i++)
#pragma unroll
        for (int j = 0; j < 4; j++)
#pragma unroll
            for (int k = 0; k < 4; k++) { acc1[i][j][k] = 0.f; acc3[i][j][k] = 0.f; }

    float4 rx[4], r1[2], r3[2];

    auto stage = [&](int kb) {
        const float* xb = xg + kb * BK;
#pragma unroll
        for (int j = 0; j < 4; j++) {
            int c = tid + j * THREADS;       // chunk 0..1023
            int row = c >> 3, k4 = c & 7;
            rx[j] = *(const float4*)(xb + (size_t)row * DIMD + k4 * 4);
        }
        const float* w1b = w1g + kb * BK;
        const float* w3b = w3g + kb * BK;
#pragma unroll
        for (int j = 0; j < 2; j++) {
            int c = tid + j * THREADS;       // chunk 0..511
            int row = c >> 3, k4 = c & 7;
            r1[j] = *(const float4*)(w1b + (size_t)row * DIMD + k4 * 4);
            r3[j] = *(const float4*)(w3b + (size_t)row * DIMD + k4 * 4);
        }
    };
    auto commit = [&](int buf) {
        uint32_t* dx = sx + buf * 4096;
#pragma unroll
        for (int j = 0; j < 4; j++) {
            int c = tid + j * THREADS; int row = c >> 3, k4 = c & 7;
            *(uint4*)(dx + schunk(row, k4)) =
                make_uint4(f2tf(rx[j].x), f2tf(rx[j].y), f2tf(rx[j].z), f2tf(rx[j].w));
        }
        uint32_t* d1 = s1 + buf * 2048;
        uint32_t* d3 = s3 + buf * 2048;
#pragma unroll
        for (int j = 0; j < 2; j++) {
            int c = tid + j * THREADS; int row = c >> 3, k4 = c & 7;
            *(uint4*)(d1 + schunk(row, k4)) =
                make_uint4(f2tf(r1[j].x), f2tf(r1[j].y), f2tf(r1[j].z), f2tf(r1[j].w));
            *(uint4*)(d3 + schunk(row, k4)) =
                make_uint4(f2tf(r3[j].x), f2tf(r3[j].y), f2tf(r3[j].z), f2tf(r3[j].w));
        }
    };

    stage(0); commit(0); __syncthreads();

    const int KITER = DIMD / BK;   // 64
    for (int kb = 0; kb < KITER; kb++) {
        if (kb + 1 < KITER) stage(kb + 1);
        const uint32_t* cx = sx + (kb & 1) * 4096;
        const uint32_t* c1 = s1 + (kb & 1) * 2048;
        const uint32_t* c3 = s3 + (kb & 1) * 2048;
#pragma unroll
        for (int kk = 0; kk < 4; kk++) {
            uint32_t af[2][4], b1f[4][2], b3f[4][2];
            const int c0 = kk * 8 + tg;
#pragma unroll
            for (int mt = 0; mt < 2; mt++) {
                int r = wm * 32 + mt * 16 + g;
                af[mt][0] = cx[sidx(r,     c0)];
                af[mt][1] = cx[sidx(r + 8, c0)];
                af[mt][2] = cx[sidx(r,     c0 + 4)];
                af[mt][3] = cx[sidx(r + 8, c0 + 4)];
            }
#pragma unroll
            for (int nt = 0; nt < 4; nt++) {
                int rn = wn * 32 + nt * 8 + g;
                b1f[nt][0] = c1[sidx(rn, c0)];
                b1f[nt][1] = c1[sidx(rn, c0 + 4)];
                b3f[nt][0] = c3[sidx(rn, c0)];
                b3f[nt][1] = c3[sidx(rn, c0 + 4)];
            }
#pragma unroll
            for (int mt = 0; mt < 2; mt++)
#pragma unroll
                for (int nt = 0; nt < 4; nt++) {
                    mma8(acc1[mt][nt], af[mt], b1f[nt]);
                    mma8(acc3[mt][nt], af[mt], b3f[nt]);
                }
        }
        if (kb + 1 < KITER) commit((kb + 1) & 1);
        __syncthreads();
    }

    // Epilogue: h = silu(a1) * a3 -> g_h (fp32)
    float* hg = g_h + (size_t)(e * CAP + m0) * HID + n0;
#pragma unroll
    for (int mt = 0; mt < 2; mt++)
#pragma unroll
        for (int nt = 0; nt < 4; nt++)
#pragma unroll
            for (int half = 0; half < 2; half++) {
                int r  = wm * 32 + mt * 16 + g + half * 8;
                int cb = wn * 32 + nt * 8 + tg * 2;
                float v1a = acc1[mt][nt][half * 2 + 0];
                float v1b = acc1[mt][nt][half * 2 + 1];
                float v3a = acc3[mt][nt][half * 2 + 0];
                float v3b = acc3[mt][nt][half * 2 + 1];
                float2 o;
                o.x = v1a / (1.f + __expf(-v1a)) * v3a;
                o.y = v1b / (1.f + __expf(-v1b)) * v3b;
                *(float2*)(hg + (size_t)r * HID + cb) = o;
            }
}

// ---------------------------------------------------------------------------
// Pass 2: out = h @ w2e^T with ragged masking + scatter placement
// grid: (DIMD/BN=32, CAP/BM=8, NE=8), block 256, dyn smem 48KB
// ---------------------------------------------------------------------------
__global__ void __launch_bounds__(THREADS, 1) moe_down(
    const int* __restrict__ cnts, const float* __restrict__ w2,
    float* __restrict__ out)
{
    extern __shared__ uint32_t sm[];
    uint32_t* sx = sm;           // 2 * 4096 (h tile 128x32)
    uint32_t* s2 = sm + 8192;    // 2 * 2048 (w2 tile 64x32)

    const int e  = blockIdx.z;
    const int n0 = blockIdx.x * BN;   // over DIMD
    const int m0 = blockIdx.y * BM;

    int start = 0, cnt = 0;
#pragma unroll
    for (int j = 0; j < NE; j++) {
        int c = cnts[j];
        if (j < e) start += c;
        if (j == e) cnt = c;
    }

    const float* hg  = g_h + (size_t)(e * CAP + m0) * HID;
    const float* w2g = w2 + (size_t)e * DIMD * HID + (size_t)n0 * HID;

    const int tid  = threadIdx.x;
    const int warp = tid >> 5, lane = tid & 31;
    const int wm = warp >> 1, wn = warp & 1;
    const int g = lane >> 2, tg = lane & 3;

    float acc[2][4][4];
#pragma unroll
    for (int i = 0; i < 2; i++)
#pragma unroll
        for (int j = 0; j < 4; j++)
#pragma unroll
            for (int k = 0; k < 4; k++) acc[i][j][k] = 0.f;

    float4 rx[4], r2[2];

    auto stage = [&](int kb) {
        const float* xb = hg + kb * BK;
#pragma unroll
        for (int j = 0; j < 4; j++) {
            int c = tid + j * THREADS;
            int row = c >> 3, k4 = c & 7;
            rx[j] = *(const float4*)(xb + (size_t)row * HID + k4 * 4);
        }
        const float* wb = w2g + kb * BK;
#pragma unroll
        for (int j = 0; j < 2; j++) {
            int c = tid + j * THREADS;
            int row = c >> 3, k4 = c & 7;
            r2[j] = *(const float4*)(wb + (size_t)row * HID + k4 * 4);
        }
    };
    auto commit = [&](int buf) {
        uint32_t* dx = sx + buf * 4096;
#pragma unroll
        for (int j = 0; j < 4; j++) {
            int c = tid + j * THREADS; int row = c >> 3, k4 = c & 7;
            *(uint4*)(dx + schunk(row, k4)) =
                make_uint4(f2tf(rx[j].x), f2tf(rx[j].y), f2tf(rx[j].z), f2tf(rx[j].w));
        }
        uint32_t* d2 = s2 + buf * 2048;
#pragma unroll
        for (int j = 0; j < 2; j++) {
            int c = tid + j * THREADS; int row = c >> 3, k4 = c & 7;
            *(uint4*)(d2 + schunk(row, k4)) =
                make_uint4(f2tf(r2[j].x), f2tf(r2[j].y), f2tf(r2[j].z), f2tf(r2[j].w));
        }
    };

    stage(0); commit(0); __syncthreads();

    const int KITER = HID / BK;   // 44
    for (int kb = 0; kb < KITER; kb++) {
        if (kb + 1 < KITER) stage(kb + 1);
        const uint32_t* cx = sx + (kb & 1) * 4096;
        const uint32_t* c2 = s2 + (kb & 1) * 2048;
#pragma unroll
        for (int kk = 0; kk < 4; kk++) {
            uint32_t af[2][4], bf[4][2];
            const int c0 = kk * 8 + tg;
#pragma unroll
            for (int mt = 0; mt < 2; mt++) {
                int r = wm * 32 + mt * 16 + g;
                af[mt][0] = cx[sidx(r,     c0)];
                af[mt][1] = cx[sidx(r + 8, c0)];
                af[mt][2] = cx[sidx(r,     c0 + 4)];
                af[mt][3] = cx[sidx(r + 8, c0 + 4)];
            }
#pragma unroll
            for (int nt = 0; nt < 4; nt++) {
                int rn = wn * 32 + nt * 8 + g;
                bf[nt][0] = c2[sidx(rn, c0)];
                bf[nt][1] = c2[sidx(rn, c0 + 4)];
            }
#pragma unroll
            for (int mt = 0; mt < 2; mt++)
#pragma unroll
                for (int nt = 0; nt < 4; nt++)
                    mma8(acc[mt][nt], af[mt], bf[nt]);
        }
        if (kb + 1 < KITER) commit((kb + 1) & 1);
        __syncthreads();
    }

    // Epilogue: masked scatter (reference zeroes rows >= cnt; out pre-zeroed)
#pragma unroll
    for (int mt = 0; mt < 2; mt++)
#pragma unroll
        for (int nt = 0; nt < 4; nt++)
#pragma unroll
            for (int half = 0; half < 2; half++) {
                int r = wm * 32 + mt * 16 + g + half * 8;
                int i = m0 + r;
                if (i < cnt) {
                    int pos = min(start + i, NT - 1);
                    int cb  = n0 + wn * 32 + nt * 8 + tg * 2;
                    float2 o;
                    o.x = acc[mt][nt][half * 2 + 0];
                    o.y = acc[mt][nt][half * 2 + 1];
                    *(float2*)(out + (size_t)pos * DIMD + cb) = o;
                }
            }
}

__global__ void zero_out_kernel(float4* o, int n4) {
    int i = blockIdx.x * blockDim.x + threadIdx.x;
    if (i < n4) o[i] = make_float4(0.f, 0.f, 0.f, 0.f);
}

extern "C" void kernel_launch(void* const* d_in, const int* in_sizes, int n_in,
                              void* d_out, int out_size) {
    (void)in_sizes; (void)n_in; (void)out_size;
    const float* x    = (const float*)d_in[0];
    const int*   cnts = (const int*)d_in[1];
    const float* w1   = (const float*)d_in[2];
    const float* w2   = (const float*)d_in[3];
    const float* w3   = (const float*)d_in[4];
    float* out = (float*)d_out;

    cudaFuncSetAttribute(moe_up,   cudaFuncAttributeMaxDynamicSharedMemorySize, 64 * 1024);
    cudaFuncSetAttribute(moe_down, cudaFuncAttributeMaxDynamicSharedMemorySize, 48 * 1024);

    const int n4 = NT * DIMD / 4;
    zero_out_kernel<<<(n4 + 255) / 256, 256>>>((float4*)out, n4);
    moe_up<<<dim3(HID / BN, CAP / BM, NE), THREADS, 64 * 1024>>>(x, cnts, w1, w3);
    moe_down<<<dim3(DIMD / BN, CAP / BM, NE), THREADS, 48 * 1024>>>(cnts, w2, out);
}

// round 3
// speedup vs baseline: 1.1948x; 1.1948x over previous
#include <cuda_runtime.h>
#include <cstdint>

#define NT   8192
#define DIMD 2048
#define HID  1408
#define NE   8
#define CAP  (NT/NE)   // 1024

#define BM 128
#define BN 64
#define BK 32
#define THREADS 256
#define NSTAGE 3

// Scratch: tf32-rounded copies of inputs + intermediate h (rounded in epilogue)
__device__ float g_xr[(size_t)NT * DIMD];
__device__ float g_w1r[(size_t)NE * HID * DIMD];
__device__ float g_w3r[(size_t)NE * HID * DIMD];
__device__ float g_w2r[(size_t)NE * DIMD * HID];
__device__ float g_h[(size_t)NT * HID];

__device__ __forceinline__ uint32_t smem_u32(const void* p) {
    uint32_t a;
    asm("{ .reg .u64 t; cvta.to.shared.u64 t, %1; cvt.u32.u64 %0, t; }" : "=r"(a) : "l"(p));
    return a;
}
__device__ __forceinline__ uint32_t f2tf(float f) {
    uint32_t u;
    asm("cvt.rna.tf32.f32 %0, %1;" : "=r"(u) : "f"(f));
    return u;
}

#define CP16(s, g)   asm volatile("cp.async.cg.shared.global [%0], [%1], 16;" :: "r"(s), "l"(g))
#define CP_COMMIT()  asm volatile("cp.async.commit_group;" ::: "memory")
#define CP_WAIT1()   asm volatile("cp.async.wait_group 1;" ::: "memory")
#define CP_WAIT0()   asm volatile("cp.async.wait_group 0;" ::: "memory")

// word index inside a [rows][32] fp32 tile, XOR-swizzled (verified in R1)
__device__ __forceinline__ int sidx(int r, int c) {
    return r * BK + ((((c >> 2) ^ (r & 7))) << 2) + (c & 3);
}

__device__ __forceinline__ void mma8(float* d, const uint32_t* a, const uint32_t* b) {
    asm volatile(
        "mma.sync.aligned.m16n8k8.row.col.f32.tf32.tf32.f32 "
        "{%0,%1,%2,%3}, {%4,%5,%6,%7}, {%8,%9}, {%0,%1,%2,%3};"
        : "+f"(d[0]), "+f"(d[1]), "+f"(d[2]), "+f"(d[3])
        : "r"(a[0]), "r"(a[1]), "r"(a[2]), "r"(a[3]), "r"(b[0]), "r"(b[1]));
}

__device__ __forceinline__ float silu(float v) { return v / (1.f + __expf(-v)); }

// ---------------------------------------------------------------------------
// Pre-round: fp32 -> tf32(RNA) bit pattern stored as fp32
// ---------------------------------------------------------------------------
__global__ void round_tf32(const float4* __restrict__ src, float4* __restrict__ dst, int n4) {
    int i = blockIdx.x * blockDim.x + threadIdx.x;
    int stride = gridDim.x * blockDim.x;
    for (; i < n4; i += stride) {
        float4 v = src[i];
        float4 o;
        o.x = __uint_as_float(f2tf(v.x));
        o.y = __uint_as_float(f2tf(v.y));
        o.z = __uint_as_float(f2tf(v.z));
        o.w = __uint_as_float(f2tf(v.w));
        dst[i] = o;
    }
}

// ---------------------------------------------------------------------------
// Pass 1: h = silu(x@w1^T) * (x@w3^T)
// grid (CAP/BM=8, HID/BN=22, NE) -- m fastest for weight-tile L2 sharing
// smem: 3 stages x (128 x-rows + 64 w1 + 64 w3) x 128B = 3 x 32KB
// ---------------------------------------------------------------------------
__global__ void __launch_bounds__(THREADS, 2) moe_up(
    const int* __restrict__ cnts)
{
    extern __shared__ uint32_t sm[];
    const uint32_t sb = smem_u32(sm);
    const int tid = threadIdx.x, warp = tid >> 5, lane = tid & 31;
    const int e = blockIdx.z, m0 = blockIdx.x * BM, n0 = blockIdx.y * BN;

    int start = 0;
#pragma unroll
    for (int j = 0; j < NE; j++) { int c = cnts[j]; if (j < e) start += c; }
    const int start_cl = min(start, NT - CAP);

    const float* xg  = g_xr  + (size_t)(start_cl + m0) * DIMD;
    const float* w1g = g_w1r + (size_t)e * HID * DIMD + (size_t)n0 * DIMD;
    const float* w3g = g_w3r + (size_t)e * HID * DIMD + (size_t)n0 * DIMD;

    const int wm = warp >> 1, wn = warp & 1;
    const int g = lane >> 2, tg = lane & 3;

    float acc1[2][4][4], acc3[2][4][4];
#pragma unroll
    for (int i = 0; i < 2; i++)
#pragma unroll
        for (int j = 0; j < 4; j++)
#pragma unroll
            for (int k = 0; k < 4; k++) { acc1[i][j][k] = 0.f; acc3[i][j][k] = 0.f; }

    // 256 rows (128 x | 64 w1 | 64 w3) x 8 chunks = 2048 / 256 thr = 8 each
    auto load_stage = [&](int c, int buf) {
        const uint32_t base = sb + buf * 32768;
        const int koff = c * BK;
#pragma unroll
        for (int j = 0; j < 8; j++) {
            int id = tid + j * THREADS;
            int row = id >> 3, k4 = id & 7;
            uint32_t sa = base + row * 128 + ((k4 ^ (row & 7)) << 4);
            const float* gp;
            if (row < 128)      gp = xg  + (size_t)row * DIMD + koff + k4 * 4;
            else if (row < 192) gp = w1g + (size_t)(row - 128) * DIMD + koff + k4 * 4;
            else                gp = w3g + (size_t)(row - 192) * DIMD + koff + k4 * 4;
            CP16(sa, gp);
        }
        CP_COMMIT();
    };

    load_stage(0, 0);
    load_stage(1, 1);

    const int KIT = DIMD / BK;   // 64
    for (int c = 0; c < KIT; c++) {
        const int s = c % NSTAGE;
        if (c + 1 < KIT) { CP_WAIT1(); } else { CP_WAIT0(); }
        __syncthreads();
        const uint32_t* cx = sm + s * 8192;
        const uint32_t* c1 = sm + s * 8192 + 4096;
        const uint32_t* c3 = sm + s * 8192 + 6144;
#pragma unroll
        for (int kk = 0; kk < 4; kk++) {
            uint32_t af[2][4], b1f[4][2], b3f[4][2];
            const int c0 = kk * 8 + tg;
#pragma unroll
            for (int mt = 0; mt < 2; mt++) {
                int r = wm * 32 + mt * 16 + g;
                af[mt][0] = cx[sidx(r,     c0)];
                af[mt][1] = cx[sidx(r + 8, c0)];
                af[mt][2] = cx[sidx(r,     c0 + 4)];
                af[mt][3] = cx[sidx(r + 8, c0 + 4)];
            }
#pragma unroll
            for (int nt = 0; nt < 4; nt++) {
                int rn = wn * 32 + nt * 8 + g;
                b1f[nt][0] = c1[sidx(rn, c0)];
                b1f[nt][1] = c1[sidx(rn, c0 + 4)];
                b3f[nt][0] = c3[sidx(rn, c0)];
                b3f[nt][1] = c3[sidx(rn, c0 + 4)];
            }
#pragma unroll
            for (int mt = 0; mt < 2; mt++)
#pragma unroll
                for (int nt = 0; nt < 4; nt++) {
                    mma8(acc1[mt][nt], af[mt], b1f[nt]);
                    mma8(acc3[mt][nt], af[mt], b3f[nt]);
                }
        }
        __syncthreads();
        if (c + 2 < KIT) load_stage(c + 2, (c + 2) % NSTAGE);
    }

    // Epilogue: h = round_tf32(silu(a1) * a3)
    float* hg = g_h + (size_t)(e * CAP + m0) * HID + n0;
#pragma unroll
    for (int mt = 0; mt < 2; mt++)
#pragma unroll
        for (int nt = 0; nt < 4; nt++)
#pragma unroll
            for (int half = 0; half < 2; half++) {
                int r  = wm * 32 + mt * 16 + g + half * 8;
                int cb = wn * 32 + nt * 8 + tg * 2;
                float v1a = acc1[mt][nt][half * 2 + 0];
                float v1b = acc1[mt][nt][half * 2 + 1];
                float v3a = acc3[mt][nt][half * 2 + 0];
                float v3b = acc3[mt][nt][half * 2 + 1];
                float2 o;
                o.x = __uint_as_float(f2tf(silu(v1a) * v3a));
                o.y = __uint_as_float(f2tf(silu(v1b) * v3b));
                *(float2*)(hg + (size_t)r * HID + cb) = o;
            }
}

// ---------------------------------------------------------------------------
// Pass 2: out = h @ w2^T, masked scatter
// grid (CAP/BM=8, DIMD/BN=32, NE), smem 3 x 24KB
// ---------------------------------------------------------------------------
__global__ void __launch_bounds__(THREADS, 3) moe_down(
    const int* __restrict__ cnts, float* __restrict__ out)
{
    extern __shared__ uint32_t sm[];
    const uint32_t sb = smem_u32(sm);
    const int tid = threadIdx.x, warp = tid >> 5, lane = tid & 31;
    const int e = blockIdx.z, m0 = blockIdx.x * BM, n0 = blockIdx.y * BN;

    int start = 0, cnt = 0;
#pragma unroll
    for (int j = 0; j < NE; j++) {
        int c = cnts[j];
        if (j < e) start += c;
        if (j == e) cnt = c;
    }

    const float* hg  = g_h + (size_t)(e * CAP + m0) * HID;
    const float* w2g = g_w2r + (size_t)e * DIMD * HID + (size_t)n0 * HID;

    const int wm = warp >> 1, wn = warp & 1;
    const int g = lane >> 2, tg = lane & 3;

    float acc[2][4][4];
#pragma unroll
    for (int i = 0; i < 2; i++)
#pragma unroll
        for (int j = 0; j < 4; j++)
#pragma unroll
            for (int k = 0; k < 4; k++) acc[i][j][k] = 0.f;

    // 192 rows (128 h | 64 w2) x 8 chunks = 1536 / 256 = 6 each
    auto load_stage = [&](int c, int buf) {
        const uint32_t base = sb + buf * 24576;
        const int koff = c * BK;
#pragma unroll
        for (int j = 0; j < 6; j++) {
            int id = tid + j * THREADS;
            int row = id >> 3, k4 = id & 7;
            uint32_t sa = base + row * 128 + ((k4 ^ (row & 7)) << 4);
            const float* gp;
            if (row < 128) gp = hg  + (size_t)row * HID + koff + k4 * 4;
            else           gp = w2g + (size_t)(row - 128) * HID + koff + k4 * 4;
            CP16(sa, gp);
        }
        CP_COMMIT();
    };

    load_stage(0, 0);
    load_stage(1, 1);

    const int KIT = HID / BK;   // 44
    for (int c = 0; c < KIT; c++) {
        const int s = c % NSTAGE;
        if (c + 1 < KIT) { CP_WAIT1(); } else { CP_WAIT0(); }
        __syncthreads();
        const uint32_t* cx = sm + s * 6144;
        const uint32_t* c2 = sm + s * 6144 + 4096;
#pragma unroll
        for (int kk = 0; kk < 4; kk++) {
            uint32_t af[2][4], bf[4][2];
            const int c0 = kk * 8 + tg;
#pragma unroll
            for (int mt = 0; mt < 2; mt++) {
                int r = wm * 32 + mt * 16 + g;
                af[mt][0] = cx[sidx(r,     c0)];
                af[mt][1] = cx[sidx(r + 8, c0)];
                af[mt][2] = cx[sidx(r,     c0 + 4)];
                af[mt][3] = cx[sidx(r + 8, c0 + 4)];
            }
#pragma unroll
            for (int nt = 0; nt < 4; nt++) {
                int rn = wn * 32 + nt * 8 + g;
                bf[nt][0] = c2[sidx(rn, c0)];
                bf[nt][1] = c2[sidx(rn, c0 + 4)];
            }
#pragma unroll
            for (int mt = 0; mt < 2; mt++)
#pragma unroll
                for (int nt = 0; nt < 4; nt++)
                    mma8(acc[mt][nt], af[mt], bf[nt]);
        }
        __syncthreads();
        if (c + 2 < KIT) load_stage(c + 2, (c + 2) % NSTAGE);
    }

#pragma unroll
    for (int mt = 0; mt < 2; mt++)
#pragma unroll
        for (int nt = 0; nt < 4; nt++)
#pragma unroll
            for (int half = 0; half < 2; half++) {
                int r = wm * 32 + mt * 16 + g + half * 8;
                int i = m0 + r;
                if (i < cnt) {
                    int pos = min(start + i, NT - 1);
                    int cb  = n0 + wn * 32 + nt * 8 + tg * 2;
                    float2 o;
                    o.x = acc[mt][nt][half * 2 + 0];
                    o.y = acc[mt][nt][half * 2 + 1];
                    *(float2*)(out + (size_t)pos * DIMD + cb) = o;
                }
            }
}

__global__ void zero_out_kernel(float4* o, int n4) {
    int i = blockIdx.x * blockDim.x + threadIdx.x;
    if (i < n4) o[i] = make_float4(0.f, 0.f, 0.f, 0.f);
}

extern "C" void kernel_launch(void* const* d_in, const int* in_sizes, int n_in,
                              void* d_out, int out_size) {
    (void)in_sizes; (void)n_in; (void)out_size;
    const float* x    = (const float*)d_in[0];
    const int*   cnts = (const int*)d_in[1];
    const float* w1   = (const float*)d_in[2];
    const float* w2   = (const float*)d_in[3];
    const float* w3   = (const float*)d_in[4];
    float* out = (float*)d_out;

    float *xr, *w1r, *w2r, *w3r;
    cudaGetSymbolAddress((void**)&xr,  g_xr);
    cudaGetSymbolAddress((void**)&w1r, g_w1r);
    cudaGetSymbolAddress((void**)&w2r, g_w2r);
    cudaGetSymbolAddress((void**)&w3r, g_w3r);

    cudaFuncSetAttribute(moe_up,   cudaFuncAttributeMaxDynamicSharedMemorySize, NSTAGE * 32768);
    cudaFuncSetAttribute(moe_down, cudaFuncAttributeMaxDynamicSharedMemorySize, NSTAGE * 24576);

    const int nx  = NT * DIMD / 4;
    const int nw  = NE * HID * DIMD / 4;
    round_tf32<<<592, 256>>>((const float4*)x,  (float4*)xr,  nx);
    round_tf32<<<592, 256>>>((const float4*)w1, (float4*)w1r, nw);
    round_tf32<<<592, 256>>>((const float4*)w2, (float4*)w2r, nw);
    round_tf32<<<592, 256>>>((const float4*)w3, (float4*)w3r, nw);

    const int n4 = NT * DIMD / 4;
    zero_out_kernel<<<(n4 + 255) / 256, 256>>>((float4*)out, n4);

    moe_up<<<dim3(CAP / BM, HID / BN, NE), THREADS, NSTAGE * 32768>>>(cnts);
    moe_down<<<dim3(CAP / BM, DIMD / BN, NE), THREADS, NSTAGE * 24576>>>(cnts, out);
}